// round 13
// baseline (speedup 1.0000x reference)
#include <cuda_runtime.h>
#include <cstdint>

// FocalLoss: loss = sum_b mean_a [ w[a] * (1-p)^2 * BCE(clamp(p), t) ]
// inputs [B, A] f32, targets [A, B] i32 (0/1), w [A] f32 -> scalar f32
//
// vs R11: BOTH streams (inputs 20KB + targets 20KB per block) staged through
// smem with lane-contiguous cp.async.cg BEFORE one barrier -> the block's
// entire DRAM demand is in flight at once; compute phase has zero GMEM
// latency exposure (the 40 latency-exposed target LDG.32s were capping
// DRAM at 75%). Fused single-node tail with release-scope wrapping atom.inc.
constexpr int BVAL = 1000000;
constexpr int AVAL = 40;
constexpr float EPSF = 1e-12f;
constexpr int TPB = 128;
constexpr int GRID = (BVAL + TPB - 1) / TPB;        // 7813
constexpr int ROW_F4 = AVAL / 4;                    // 10 float4 per row
constexpr int TILE_F4 = TPB * ROW_F4;               // 1280 f4 input chunks
constexpr int TGT_I4  = AVAL * TPB / 4;             // 1280 int4 target chunks
constexpr long TOTAL_F4 = (long)BVAL * ROW_F4;      // 10e6

__device__ double g_acc;            // zero at load; reset by last block each launch
__device__ unsigned int g_count;    // zero at load; self-resets via inc-wrap

__device__ __forceinline__ uint32_t smem_u32(const void* p) {
    uint32_t a;
    asm("{ .reg .u64 t; cvta.to.shared.u64 t, %1; cvt.u32.u64 %0, t; }"
        : "=r"(a) : "l"(p));
    return a;
}

__global__ void __launch_bounds__(TPB) focal_fused_kernel(
    const float* __restrict__ inputs,
    const int*   __restrict__ targets,
    const float* __restrict__ w,
    float* __restrict__ out)
{
    __shared__ float4 s4[TILE_F4];     // 20 KB: block's 128 input rows
    __shared__ int    st[AVAL * TPB];  // 20 KB: st[a*128 + b_local]
    __shared__ float  sw[AVAL];

    int tid = threadIdx.x;
    if (tid < AVAL) sw[tid] = w[tid];

    // --- Stage input slab: lane-contiguous 16B async copies ---
    long base_f4 = (long)blockIdx.x * TILE_F4;
    const float4* in4 = reinterpret_cast<const float4*>(inputs);
    #pragma unroll
    for (int i = 0; i < ROW_F4; i++) {
        int  sidx = tid + i * TPB;
        long gidx = base_f4 + sidx;
        if (gidx < TOTAL_F4) {
            uint32_t dst = smem_u32(&s4[sidx]);
            asm volatile("cp.async.cg.shared.global [%0], [%1], 16;"
                         :: "r"(dst), "l"(in4 + gidx) : "memory");
        } else {
            s4[sidx] = make_float4(0.f, 0.f, 0.f, 0.f);
        }
    }

    // --- Stage target slab: 40 attrs x 128 b x 4B = 20KB, 16B chunks ---
    // chunk c: attr a = c>>5, inner = c&31 (inner*4 = b offset within block)
    long bbase = (long)blockIdx.x * TPB;
    #pragma unroll
    for (int i = 0; i < AVAL / 4; i++) {            // 10 chunks per thread
        int c = tid + i * TPB;
        int a = c >> 5;
        int inner = c & 31;
        long gb = bbase + inner * 4;                 // first of 4 b's in chunk
        uint32_t dst = smem_u32(&st[a * TPB + inner * 4]);
        if (gb + 3 < BVAL) {
            asm volatile("cp.async.cg.shared.global [%0], [%1], 16;"
                         :: "r"(dst), "l"(targets + (long)a * BVAL + gb) : "memory");
        } else {
            #pragma unroll
            for (int k = 0; k < 4; k++)
                st[a * TPB + inner * 4 + k] =
                    (gb + k < BVAL) ? targets[(long)a * BVAL + gb + k] : 0;
        }
    }
    asm volatile("cp.async.commit_group;" ::: "memory");
    asm volatile("cp.async.wait_group 0;" ::: "memory");
    __syncthreads();

    int b = blockIdx.x * TPB + tid;
    float acc = 0.0f;
    if (b < BVAL) {
        #pragma unroll
        for (int a4 = 0; a4 < ROW_F4; a4++) {
            float4 p4 = s4[tid * ROW_F4 + a4];          // own row (2-way max)
            float pv[4] = {p4.x, p4.y, p4.z, p4.w};
            #pragma unroll
            for (int j = 0; j < 4; j++) {
                int a = a4 * 4 + j;
                int t = st[a * TPB + tid];              // conflict-free LDS.32
                float p  = pv[j];
                float pc = fminf(fmaxf(p, EPSF), 1.0f - EPSF);
                float arg = t ? pc : (1.0f - pc);   // t is 0/1: one log suffices
                float bce = -__logf(arg);           // MUFU.LG2 path
                float om  = 1.0f - p;               // focal weight uses UNCLAMPED p
                acc = fmaf(sw[a] * om * om, bce, acc);
            }
        }
    }

    // warp reduce
    #pragma unroll
    for (int off = 16; off; off >>= 1)
        acc += __shfl_down_sync(0xffffffffu, acc, off);

    __shared__ float warpsum[TPB / 32];
    if ((tid & 31) == 0) warpsum[tid >> 5] = acc;
    __syncthreads();

    if (tid < TPB / 32) {
        float v = warpsum[tid];
        #pragma unroll
        for (int off = (TPB / 64); off; off >>= 1)
            v += __shfl_down_sync(0xfu, v, off);
        if (tid == 0) {
            atomicAdd(&g_acc, (double)v);
            unsigned int old;
            asm volatile("atom.release.gpu.global.inc.u32 %0, [%1], %2;"
                         : "=r"(old)
                         : "l"(&g_count), "r"((unsigned)(GRID - 1))
                         : "memory");
            if (old == (unsigned)(GRID - 1)) {
                double tot;
                asm volatile("ld.acquire.gpu.global.f64 %0, [%1];"
                             : "=d"(tot) : "l"(&g_acc) : "memory");
                out[0] = (float)(tot * (1.0 / (double)AVAL));
                asm volatile("st.relaxed.gpu.global.f64 [%0], %1;"
                             :: "l"(&g_acc), "d"(0.0) : "memory");
            }
        }
    }
}

extern "C" void kernel_launch(void* const* d_in, const int* in_sizes, int n_in,
                              void* d_out, int out_size)
{
    const float* inputs  = (const float*)d_in[0];   // [B, A]
    const int*   targets = (const int*)  d_in[1];   // [A, B]
    const float* weights = (const float*)d_in[2];   // [A]

    focal_fused_kernel<<<GRID, TPB>>>(inputs, targets, weights, (float*)d_out);
}

// round 14
// speedup vs baseline: 1.0240x; 1.0240x over previous
#include <cuda_runtime.h>
#include <cstdint>

// FocalLoss: loss = sum_b mean_a [ w[a] * (1-p)^2 * BCE(clamp(p), t) ]
// inputs [B, A] f32, targets [A, B] i32 (0/1), w [A] f32 -> scalar f32
//
// vs R10 (measured best 53.7us): the ONLY change is input staging -- one
// cp.async.bulk (UBLKCP, 40KB contiguous) per block instead of 2560
// per-thread LDGSTS, freeing LSU/L1tex issue for the target LDG stream.
// Last (partial) block falls back to guarded per-thread cp.async.
// Targets direct __ldcs; fused single-node tail with release-scope
// wrapping atom.inc (no threadfence / no L1 flush).
constexpr int BVAL = 1000000;
constexpr int AVAL = 40;
constexpr float EPSF = 1e-12f;
constexpr int TPB = 256;
constexpr int GRID = (BVAL + TPB - 1) / TPB;        // 3907
constexpr int ROW_F4 = AVAL / 4;                    // 10 float4 per row
constexpr int TILE_F4 = TPB * ROW_F4;               // 2560 float4 per block
constexpr int TILE_BYTES = TILE_F4 * 16;            // 40960
constexpr long TOTAL_F4 = (long)BVAL * ROW_F4;      // 10e6

__device__ double g_acc;            // zero at load; reset by last block each launch
__device__ unsigned int g_count;    // zero at load; self-resets via inc-wrap

__device__ __forceinline__ uint32_t smem_u32(const void* p) {
    uint32_t a;
    asm("{ .reg .u64 t; cvta.to.shared.u64 t, %1; cvt.u32.u64 %0, t; }"
        : "=r"(a) : "l"(p));
    return a;
}

__global__ void __launch_bounds__(TPB) focal_fused_kernel(
    const float* __restrict__ inputs,
    const int*   __restrict__ targets,
    const float* __restrict__ w,
    float* __restrict__ out)
{
    __shared__ alignas(128) float4 s4[TILE_F4];   // 40 KB input tile
    __shared__ float     sw[AVAL];
    __shared__ uint64_t  mbar;

    int tid = threadIdx.x;
    if (tid < AVAL) sw[tid] = w[tid];

    long base_f4 = (long)blockIdx.x * TILE_F4;
    const float4* in4 = reinterpret_cast<const float4*>(inputs);
    bool full_tile = (base_f4 + TILE_F4 <= TOTAL_F4);

    if (full_tile) {
        // --- TMA-style bulk staging: one UBLKCP for the whole 40KB tile ---
        uint32_t mb = smem_u32(&mbar);
        if (tid == 0) {
            asm volatile("mbarrier.init.shared.b64 [%0], 1;" :: "r"(mb) : "memory");
            asm volatile("fence.proxy.async.shared::cta;" ::: "memory");
            asm volatile("mbarrier.arrive.expect_tx.shared.b64 _, [%0], %1;"
                         :: "r"(mb), "r"((unsigned)TILE_BYTES) : "memory");
            asm volatile(
                "cp.async.bulk.shared::cluster.global.mbarrier::complete_tx::bytes "
                "[%0], [%1], %2, [%3];"
                :: "r"(smem_u32(s4)), "l"(in4 + base_f4),
                   "r"((unsigned)TILE_BYTES), "r"(mb) : "memory");
        }
        __syncthreads();
        // wait (parity 0: barrier freshly initialized each launch)
        {
            uint32_t done;
            asm volatile(
                "{\n\t.reg .pred p;\n\t"
                "WAITL_%=:\n\t"
                "mbarrier.try_wait.parity.acquire.cta.shared::cta.b64 p, [%1], 0, 0x989680;\n\t"
                "selp.b32 %0, 1, 0, p;\n\t"
                "@!p bra.uni WAITL_%=;\n\t}"
                : "=r"(done) : "r"(smem_u32(&mbar)) : "memory");
        }
    } else {
        // --- partial last block: guarded per-thread cp.async (R10 path) ---
        #pragma unroll
        for (int i = 0; i < ROW_F4; i++) {
            int  sidx = tid + i * TPB;
            long gidx = base_f4 + sidx;
            if (gidx < TOTAL_F4) {
                uint32_t dst = smem_u32(&s4[sidx]);
                asm volatile("cp.async.cg.shared.global [%0], [%1], 16;"
                             :: "r"(dst), "l"(in4 + gidx) : "memory");
            } else {
                s4[sidx] = make_float4(0.f, 0.f, 0.f, 0.f);
            }
        }
        asm volatile("cp.async.commit_group;" ::: "memory");
        asm volatile("cp.async.wait_group 0;" ::: "memory");
        __syncthreads();
    }

    int b = blockIdx.x * TPB + tid;
    float acc = 0.0f;
    if (b < BVAL) {
        #pragma unroll
        for (int a4 = 0; a4 < ROW_F4; a4++) {
            float4 p4 = s4[tid * ROW_F4 + a4];          // own row from smem
            float pv[4] = {p4.x, p4.y, p4.z, p4.w};
            #pragma unroll
            for (int j = 0; j < 4; j++) {
                int a = a4 * 4 + j;
                int t = __ldcs(targets + (long)a * BVAL + b);  // coalesced per a
                float p  = pv[j];
                float pc = fminf(fmaxf(p, EPSF), 1.0f - EPSF);
                float arg = t ? pc : (1.0f - pc);   // t is 0/1: one log suffices
                float bce = -__logf(arg);           // MUFU.LG2 path
                float om  = 1.0f - p;               // focal weight uses UNCLAMPED p
                acc = fmaf(sw[a] * om * om, bce, acc);
            }
        }
    }

    // warp reduce
    #pragma unroll
    for (int off = 16; off; off >>= 1)
        acc += __shfl_down_sync(0xffffffffu, acc, off);

    __shared__ float warpsum[TPB / 32];
    if ((tid & 31) == 0) warpsum[tid >> 5] = acc;
    __syncthreads();

    if (tid < TPB / 32) {
        float v = warpsum[tid];
        #pragma unroll
        for (int off = (TPB / 64); off; off >>= 1)
            v += __shfl_down_sync(0xffu, v, off);
        if (tid == 0) {
            atomicAdd(&g_acc, (double)v);
            // Release-scope wrapping inc: orders the g_acc add, no L1 flush.
            unsigned int old;
            asm volatile("atom.release.gpu.global.inc.u32 %0, [%1], %2;"
                         : "=r"(old)
                         : "l"(&g_count), "r"((unsigned)(GRID - 1))
                         : "memory");
            if (old == (unsigned)(GRID - 1)) {
                double tot;
                asm volatile("ld.acquire.gpu.global.f64 %0, [%1];"
                             : "=d"(tot) : "l"(&g_acc) : "memory");
                out[0] = (float)(tot * (1.0 / (double)AVAL));
                asm volatile("st.relaxed.gpu.global.f64 [%0], %1;"
                             :: "l"(&g_acc), "d"(0.0) : "memory");
            }
        }
    }
}

extern "C" void kernel_launch(void* const* d_in, const int* in_sizes, int n_in,
                              void* d_out, int out_size)
{
    const float* inputs  = (const float*)d_in[0];   // [B, A]
    const int*   targets = (const int*)  d_in[1];   // [A, B]
    const float* weights = (const float*)d_in[2];   // [A]

    focal_fused_kernel<<<GRID, TPB>>>(inputs, targets, weights, (float*)d_out);
}